// round 1
// baseline (speedup 1.0000x reference)
#include <cuda_runtime.h>

// Problem dims (fixed by setup_inputs)
#define B_  8
#define H_  128
#define W_  128
#define C_  64
#define K2_ 9
#define F_  128

// Scratch for predicted offsets: [B,H,W,18]  (9.4 MB)
__device__ float g_offsets[B_ * H_ * W_ * 2 * K2_];

// ---------------------------------------------------------------------------
// Kernel 1: 3x3 SAME conv, 64 -> 18 channels (offset predictor)
// One block per (b, y) row; 128 threads = one per x pixel.
// Per dy: stage the input row (zero-padded horizontally) + the dy-slice of
// w_off in SMEM, then accumulate 18 outputs per thread in registers.
// ---------------------------------------------------------------------------
__global__ __launch_bounds__(128) void offset_conv_kernel(
    const float* __restrict__ x, const float* __restrict__ w_off,
    const float* __restrict__ b_off)
{
    __shared__ float row_sh[130 * 68];      // padded row: entries 0..129, stride 68 (16B-aligned)
    __shared__ float w_sh[3 * 64 * 18];     // one dy slice: [dx][c][oc]

    const int t  = threadIdx.x;             // pixel x (0..127)
    const int by = blockIdx.x;              // b*H + y
    const int b  = by / H_;
    const int y  = by % H_;

    float acc[18];
    #pragma unroll
    for (int oc = 0; oc < 18; oc++) acc[oc] = b_off[oc];

    for (int dy = 0; dy < 3; dy++) {
        __syncthreads();   // protect previous iteration's reads
        const int yy = y + dy - 1;

        // stage w slice for this dy
        for (int i = t; i < 3 * 64 * 18; i += 128)
            w_sh[i] = w_off[dy * 3 * 64 * 18 + i];

        // zero left/right pad entries
        if (t < 2) {
            const int e = (t == 0) ? 0 : 129;
            float4 z = make_float4(0.f, 0.f, 0.f, 0.f);
            #pragma unroll
            for (int c = 0; c < 64; c += 4)
                *(float4*)&row_sh[e * 68 + c] = z;
        }
        // stage the input row (or zeros if vertically out of range)
        {
            float4* dst = (float4*)&row_sh[(t + 1) * 68];
            if (yy >= 0 && yy < H_) {
                const float4* src = (const float4*)&x[((b * H_ + yy) * W_ + t) * C_];
                #pragma unroll
                for (int c = 0; c < 16; c++) dst[c] = src[c];
            } else {
                float4 z = make_float4(0.f, 0.f, 0.f, 0.f);
                #pragma unroll
                for (int c = 0; c < 16; c++) dst[c] = z;
            }
        }
        __syncthreads();

        for (int dx = 0; dx < 3; dx++) {
            const float* wp = &w_sh[dx * 64 * 18];
            const float* rp = &row_sh[(t + dx) * 68];   // pixel (t + dx - 1), padded index t+dx
            for (int c = 0; c < 64; c++) {
                const float xv = rp[c];
                #pragma unroll
                for (int oc = 0; oc < 18; oc++)
                    acc[oc] += xv * wp[c * 18 + oc];
            }
        }
    }

    float* op = &g_offsets[((b * H_ + y) * W_ + t) * 18];
    #pragma unroll
    for (int oc = 0; oc < 18; oc++) op[oc] = acc[oc];
}

// ---------------------------------------------------------------------------
// Kernel 2: fused bilinear sampling + 1x1 conv (GEMM M=131072, K=576, N=128)
// Block = 64-pixel M tile x full N=128. 256 threads, 4x8 register tile.
// K processed in 18 chunks of 32 (half a tap each). The A tile (sampled
// features) is generated on the fly from x + g_offsets.
// ---------------------------------------------------------------------------
__global__ __launch_bounds__(256) void dconv_gemm_kernel(
    const float* __restrict__ x, const float* __restrict__ w_out,
    const float* __restrict__ b_out, float* __restrict__ out)
{
    __shared__ float B_sh[32 * 128];   // w_out chunk  [kk][n]
    __shared__ float A_sh[32 * 68];    // sampled tile [kk][m], padded stride 68

    const int tid = threadIdx.x;
    const int tx = tid & 15;           // n-dim thread coord
    const int ty = tid >> 4;           // m-dim thread coord
    const int n0 = tx * 8;
    const int m0 = ty * 4;

    const int p0 = blockIdx.x * 64;    // first pixel of this tile (same row)
    const int b  = p0 >> 14;
    const int y  = (p0 >> 7) & 127;
    const int x0 = p0 & 127;

    // A-generation mapping: 4 threads per pixel, 8 channels each
    const int pm = tid >> 2;           // pixel within tile (0..63)
    const int cg = tid & 3;            // channel group (8 channels)

    float acc[4][8];
    #pragma unroll
    for (int i = 0; i < 4; i++)
        #pragma unroll
        for (int j = 0; j < 8; j++) acc[i][j] = b_out[n0 + j];

    const int gx   = x0 + pm;
    const int gpix = (b * H_ + y) * W_ + gx;
    const float* xb = x + b * H_ * W_ * C_;

    for (int ch = 0; ch < 18; ch++) {
        const int tap   = ch >> 1;
        const int chalf = ch & 1;
        __syncthreads();   // protect previous chunk's GEMM reads

        // --- stage B chunk: w_out rows [ch*32, ch*32+32) ---
        {
            const float4* src = (const float4*)&w_out[ch * 32 * 128];
            float4* dst = (float4*)B_sh;
            #pragma unroll
            for (int i = 0; i < 4; i++)
                dst[tid + i * 256] = src[tid + i * 256];
        }

        // --- build A chunk: bilinear sample 8 channels of one pixel/tap ---
        {
            const float xoff = g_offsets[gpix * 18 + tap * 2 + 0];
            const float yoff = g_offsets[gpix * 18 + tap * 2 + 1];
            const float nx = fminf(fmaxf((float)gx + xoff, 0.f), (float)(W_ - 1));
            const float ny = fminf(fmaxf((float)y  + yoff, 0.f), (float)(H_ - 1));
            const float x0f = floorf(nx);
            const float y0f = floorf(ny);
            const float x1f = fminf(x0f + 1.f, (float)(W_ - 1));
            const float y1f = fminf(y0f + 1.f, (float)(H_ - 1));
            const float lx = nx - x0f, hx = x1f - nx;
            const float ly = ny - y0f, hy = y1f - ny;
            const float wa = hx * hy, wb = hx * ly, wc = lx * hy, wd = lx * ly;
            const int ix0 = (int)x0f, ix1 = (int)x1f;
            const int iy0 = (int)y0f, iy1 = (int)y1f;

            const int cbase = chalf * 32 + cg * 8;
            const float4* p00 = (const float4*)&xb[(iy0 * W_ + ix0) * C_ + cbase];
            const float4* p10 = (const float4*)&xb[(iy1 * W_ + ix0) * C_ + cbase];
            const float4* p01 = (const float4*)&xb[(iy0 * W_ + ix1) * C_ + cbase];
            const float4* p11 = (const float4*)&xb[(iy1 * W_ + ix1) * C_ + cbase];

            #pragma unroll
            for (int q = 0; q < 2; q++) {
                const float4 a  = p00[q];
                const float4 bb = p10[q];
                const float4 cc = p01[q];
                const float4 dd = p11[q];
                const float v0 = wa * a.x + wb * bb.x + wc * cc.x + wd * dd.x;
                const float v1 = wa * a.y + wb * bb.y + wc * cc.y + wd * dd.y;
                const float v2 = wa * a.z + wb * bb.z + wc * cc.z + wd * dd.z;
                const float v3 = wa * a.w + wb * bb.w + wc * cc.w + wd * dd.w;
                const int k = cg * 8 + q * 4;   // chunk-local channel
                A_sh[(k + 0) * 68 + pm] = v0;
                A_sh[(k + 1) * 68 + pm] = v1;
                A_sh[(k + 2) * 68 + pm] = v2;
                A_sh[(k + 3) * 68 + pm] = v3;
            }
        }
        __syncthreads();

        // --- GEMM: acc[4][8] += A[kk][m0..3] * B[kk][n0..7] ---
        #pragma unroll 4
        for (int kk = 0; kk < 32; kk++) {
            const float4 a  = *(const float4*)&A_sh[kk * 68 + m0];
            const float4 b0 = *(const float4*)&B_sh[kk * 128 + n0];
            const float4 b1 = *(const float4*)&B_sh[kk * 128 + n0 + 4];
            const float am[4] = {a.x, a.y, a.z, a.w};
            const float bn[8] = {b0.x, b0.y, b0.z, b0.w, b1.x, b1.y, b1.z, b1.w};
            #pragma unroll
            for (int i = 0; i < 4; i++)
                #pragma unroll
                for (int j = 0; j < 8; j++)
                    acc[i][j] += am[i] * bn[j];
        }
    }

    // --- store out tile [B,H,W,F] ---
    float* op = out + (p0 + m0) * F_ + n0;
    #pragma unroll
    for (int i = 0; i < 4; i++) {
        *(float4*)&op[i * F_ + 0] = make_float4(acc[i][0], acc[i][1], acc[i][2], acc[i][3]);
        *(float4*)&op[i * F_ + 4] = make_float4(acc[i][4], acc[i][5], acc[i][6], acc[i][7]);
    }
}

// ---------------------------------------------------------------------------
extern "C" void kernel_launch(void* const* d_in, const int* in_sizes, int n_in,
                              void* d_out, int out_size)
{
    const float* x     = (const float*)d_in[0];   // [8,128,128,64]
    const float* w_off = (const float*)d_in[1];   // [3,3,64,18]
    const float* b_off = (const float*)d_in[2];   // [18]
    const float* w_out = (const float*)d_in[3];   // [576,128]
    const float* b_out = (const float*)d_in[4];   // [128]
    float* out = (float*)d_out;                   // [8,128,128,128]

    offset_conv_kernel<<<B_ * H_, 128>>>(x, w_off, b_off);
    dconv_gemm_kernel<<<(B_ * H_ * W_) / 64, 256>>>(x, w_out, b_out, out);
}

// round 3
// speedup vs baseline: 1.6878x; 1.6878x over previous
#include <cuda_runtime.h>
#include <cstdint>

#define B_  8
#define H_  128
#define W_  128
#define C_  64
#define F_  128

// scratch
__device__ float g_offsets[B_*H_*W_*18];   // predicted offsets [B,H,W,18]
__device__ float g_wT[576*128];            // w_out, tf32-rounded (same layout)

__device__ __forceinline__ uint32_t f2tf32(float f){
    uint32_t r; asm("cvt.rna.tf32.f32 %0, %1;" : "=r"(r) : "f"(f)); return r;
}

// ---------------------------------------------------------------------------
// Prep: round w_out to tf32 elementwise (layout unchanged: [576][128])
// ---------------------------------------------------------------------------
__global__ void prep_w_kernel(const float* __restrict__ w_out)
{
    int idx = blockIdx.x * 256 + threadIdx.x;
    if (idx < 576*128) g_wT[idx] = __uint_as_float(f2tf32(w_out[idx]));
}

// ---------------------------------------------------------------------------
// Kernel 1: 3x3 SAME conv, 64 -> 18 channels (offset predictor)  [unchanged]
// ---------------------------------------------------------------------------
__global__ __launch_bounds__(128) void offset_conv_kernel(
    const float* __restrict__ x, const float* __restrict__ w_off,
    const float* __restrict__ b_off)
{
    __shared__ float row_sh[130 * 68];
    __shared__ float w_sh[3 * 64 * 18];

    const int t  = threadIdx.x;
    const int by = blockIdx.x;
    const int b  = by / H_;
    const int y  = by % H_;

    float acc[18];
    #pragma unroll
    for (int oc = 0; oc < 18; oc++) acc[oc] = b_off[oc];

    for (int dy = 0; dy < 3; dy++) {
        __syncthreads();
        const int yy = y + dy - 1;
        for (int i = t; i < 3 * 64 * 18; i += 128)
            w_sh[i] = w_off[dy * 3 * 64 * 18 + i];
        if (t < 2) {
            const int e = (t == 0) ? 0 : 129;
            float4 z = make_float4(0.f, 0.f, 0.f, 0.f);
            #pragma unroll
            for (int c = 0; c < 64; c += 4)
                *(float4*)&row_sh[e * 68 + c] = z;
        }
        {
            float4* dst = (float4*)&row_sh[(t + 1) * 68];
            if (yy >= 0 && yy < H_) {
                const float4* src = (const float4*)&x[((b * H_ + yy) * W_ + t) * C_];
                #pragma unroll
                for (int c = 0; c < 16; c++) dst[c] = src[c];
            } else {
                float4 z = make_float4(0.f, 0.f, 0.f, 0.f);
                #pragma unroll
                for (int c = 0; c < 16; c++) dst[c] = z;
            }
        }
        __syncthreads();

        for (int dx = 0; dx < 3; dx++) {
            const float* wp = &w_sh[dx * 64 * 18];
            const float* rp = &row_sh[(t + dx) * 68];
            for (int c = 0; c < 64; c++) {
                const float xv = rp[c];
                #pragma unroll
                for (int oc = 0; oc < 18; oc++)
                    acc[oc] += xv * wp[c * 18 + oc];
            }
        }
    }
    float* op = &g_offsets[((b * H_ + y) * W_ + t) * 18];
    #pragma unroll
    for (int oc = 0; oc < 18; oc++) op[oc] = acc[oc];
}

// ---------------------------------------------------------------------------
// Kernel 2: fused bilinear sampling + tensor-core tf32 GEMM (mma.sync)
// Block = 128 pixels x N=128. 8 warps, warp tile 64x32, K=576 in 18x32 chunks.
// ---------------------------------------------------------------------------
#define SA 136   // smem row stride (floats); 136%32==8 -> conflict-free frags

__device__ __forceinline__ void mma_tf32(float* d, const uint32_t* a, const uint32_t* bb){
    asm volatile(
      "mma.sync.aligned.m16n8k8.row.col.f32.tf32.tf32.f32 "
      "{%0,%1,%2,%3}, {%4,%5,%6,%7}, {%8,%9}, {%0,%1,%2,%3};"
      : "+f"(d[0]),"+f"(d[1]),"+f"(d[2]),"+f"(d[3])
      : "r"(a[0]),"r"(a[1]),"r"(a[2]),"r"(a[3]),"r"(bb[0]),"r"(bb[1]));
}

__global__ __launch_bounds__(256, 2) void dconv_gemm_mma(
    const float* __restrict__ x, const float* __restrict__ b_out,
    float* __restrict__ out)
{
    __shared__ float A_sh[32 * SA];
    __shared__ float B_sh[32 * SA];
    __shared__ float bias_sh[128];

    const int tid  = threadIdx.x;
    const int wid  = tid >> 5;
    const int lane = tid & 31;
    const int g  = lane >> 2;       // groupID
    const int tc = lane & 3;        // thread-in-group

    if (tid < 128) bias_sh[tid] = b_out[tid];

    const int p0 = blockIdx.x * 128;     // one image row of pixels
    const int y  = (p0 >> 7) & 127;
    const int b  = p0 >> 14;
    const int pm = tid & 127;            // pixel within tile
    const int h  = tid >> 7;             // 16-channel half of a 32-chunk
    const float* xb = x + b * H_ * W_ * C_;
    const int gpix = p0 + pm;

    // warp tiling: 2 (M) x 4 (N); warp tile 64x32
    const int m_base = (wid >> 2) * 64;
    const int n_base = (wid & 3) * 32;
    __syncthreads();                     // bias visible

    float acc[4][4][4];                  // [mf][nf][reg]
    #pragma unroll
    for (int nf = 0; nf < 4; nf++) {
        const int c0 = n_base + nf * 8 + 2 * tc;
        const float bz0 = bias_sh[c0], bz1 = bias_sh[c0 + 1];
        #pragma unroll
        for (int mf = 0; mf < 4; mf++) {
            acc[mf][nf][0] = bz0; acc[mf][nf][1] = bz1;
            acc[mf][nf][2] = bz0; acc[mf][nf][3] = bz1;
        }
    }

    float wa = 0.f, wbv = 0.f, wcv = 0.f, wdv = 0.f;
    int i00 = 0, i10 = 0, i01 = 0, i11 = 0;

    for (int ch = 0; ch < 18; ch++) {
        const int tap   = ch >> 1;
        const int chalf = ch & 1;

        // ---- sample 16 channels of pixel pm into registers (overlaps MMA) ----
        if (chalf == 0) {
            float2 off = *(const float2*)&g_offsets[gpix * 18 + tap * 2];
            float nx = fminf(fmaxf((float)pm + off.x, 0.f), 127.f);
            float ny = fminf(fmaxf((float)y  + off.y, 0.f), 127.f);
            float x0f = floorf(nx), y0f = floorf(ny);
            float x1f = fminf(x0f + 1.f, 127.f), y1f = fminf(y0f + 1.f, 127.f);
            float lx = nx - x0f, hx = x1f - nx;
            float ly = ny - y0f, hy = y1f - ny;
            wa  = hx * hy; wbv = hx * ly; wcv = lx * hy; wdv = lx * ly;
            int ix0 = (int)x0f, ix1 = (int)x1f, iy0 = (int)y0f, iy1 = (int)y1f;
            i00 = (iy0 * W_ + ix0) * C_;  i10 = (iy1 * W_ + ix0) * C_;
            i01 = (iy0 * W_ + ix1) * C_;  i11 = (iy1 * W_ + ix1) * C_;
        }
        uint32_t vv[16];
        {
            const int cb = chalf * 32 + h * 16;
            const float* q00 = xb + i00 + cb;
            const float* q10 = xb + i10 + cb;
            const float* q01 = xb + i01 + cb;
            const float* q11 = xb + i11 + cb;
            #pragma unroll
            for (int j = 0; j < 4; j++) {
                float4 a  = *(const float4*)(q00 + j * 4);
                float4 bb = *(const float4*)(q10 + j * 4);
                float4 cc = *(const float4*)(q01 + j * 4);
                float4 dd = *(const float4*)(q11 + j * 4);
                vv[j*4+0] = f2tf32(wa*a.x + wbv*bb.x + wcv*cc.x + wdv*dd.x);
                vv[j*4+1] = f2tf32(wa*a.y + wbv*bb.y + wcv*cc.y + wdv*dd.y);
                vv[j*4+2] = f2tf32(wa*a.z + wbv*bb.z + wcv*cc.z + wdv*dd.z);
                vv[j*4+3] = f2tf32(wa*a.w + wbv*bb.w + wcv*cc.w + wdv*dd.w);
            }
        }

        __syncthreads();   // previous chunk fully consumed

        // ---- store A chunk [k][m]; warp = 32 consecutive pixels, same k ----
        #pragma unroll
        for (int j = 0; j < 4; j++)
            #pragma unroll
            for (int c = 0; c < 4; c++)
                A_sh[(h*16 + j*4 + c) * SA + pm] = __uint_as_float(vv[j*4+c]);

        // ---- stage B chunk: rows [ch*32, ch*32+32) of g_wT into [k][n] ----
        {
            const float4* src = (const float4*)&g_wT[ch * 32 * 128];
            #pragma unroll
            for (int i = 0; i < 4; i++) {
                int idx = tid + i * 256;            // 1024 float4s
                int kk = idx >> 5, n4 = idx & 31;
                float4 v = src[idx];
                *(float4*)&B_sh[kk * SA + n4 * 4] = v;
            }
        }

        __syncthreads();   // staging visible

        // ---- 4 x K=8 mma steps ----
        #pragma unroll
        for (int s = 0; s < 4; s++) {
            const int k0 = s * 8;
            const uint32_t* Ar0 = (const uint32_t*)&A_sh[(k0 + tc)     * SA];
            const uint32_t* Ar1 = (const uint32_t*)&A_sh[(k0 + tc + 4) * SA];
            const uint32_t* Br0 = (const uint32_t*)&B_sh[(k0 + tc)     * SA];
            const uint32_t* Br1 = (const uint32_t*)&B_sh[(k0 + tc + 4) * SA];

            uint32_t afr[4][4];
            #pragma unroll
            for (int mf = 0; mf < 4; mf++) {
                const int m = m_base + mf * 16 + g;
                afr[mf][0] = Ar0[m];     afr[mf][1] = Ar0[m + 8];
                afr[mf][2] = Ar1[m];     afr[mf][3] = Ar1[m + 8];
            }
            uint32_t bfr[4][2];
            #pragma unroll
            for (int nf = 0; nf < 4; nf++) {
                const int n = n_base + nf * 8 + g;
                bfr[nf][0] = Br0[n];     bfr[nf][1] = Br1[n];
            }
            #pragma unroll
            for (int mf = 0; mf < 4; mf++)
                #pragma unroll
                for (int nf = 0; nf < 4; nf++)
                    mma_tf32(acc[mf][nf], afr[mf], bfr[nf]);
        }
    }

    // ---- epilogue: registers -> gmem ----
    #pragma unroll
    for (int mf = 0; mf < 4; mf++) {
        const int row = p0 + m_base + mf * 16 + g;
        #pragma unroll
        for (int nf = 0; nf < 4; nf++) {
            const int col = n_base + nf * 8 + 2 * tc;
            *(float2*)&out[(size_t)row * F_ + col] =
                make_float2(acc[mf][nf][0], acc[mf][nf][1]);
            *(float2*)&out[(size_t)(row + 8) * F_ + col] =
                make_float2(acc[mf][nf][2], acc[mf][nf][3]);
        }
    }
}

// ---------------------------------------------------------------------------
extern "C" void kernel_launch(void* const* d_in, const int* in_sizes, int n_in,
                              void* d_out, int out_size)
{
    const float* x     = (const float*)d_in[0];
    const float* w_off = (const float*)d_in[1];
    const float* b_off = (const float*)d_in[2];
    const float* w_out = (const float*)d_in[3];
    const float* b_out = (const float*)d_in[4];
    float* out = (float*)d_out;

    prep_w_kernel<<<(576*128 + 255)/256, 256>>>(w_out);
    offset_conv_kernel<<<B_ * H_, 128>>>(x, w_off, b_off);
    dconv_gemm_mma<<<(B_ * H_ * W_) / 128, 256>>>(x, b_out, out);
}

// round 4
// speedup vs baseline: 1.7182x; 1.0180x over previous
#include <cuda_runtime.h>
#include <cstdint>

#define B_  8
#define H_  128
#define W_  128
#define C_  64
#define F_  128
#define SA  136   // A smem row stride (floats): 136%32==8 -> conflict-free frags
#define SBW 36    // k1 B smem row stride: 36%32==4 -> conflict-free (4*tc+g)

// scratch
__device__ float  g_offsets[B_*H_*W_*18];     // predicted offsets [B,H,W,18]
__device__ float  g_wT[576*128];              // w_out, tf32-rounded  [k][n]
__device__ float  g_wOffP[576*SBW];           // w_off, tf32, padded  [k][36] (n>=18 zero)
__device__ float4 g_xT[B_*16*H_*W_];          // x channel-blocked [b][c/4][y][x] (33.5MB)

__device__ __forceinline__ uint32_t f2tf32(float f){
    uint32_t r; asm("cvt.rna.tf32.f32 %0, %1;" : "=r"(r) : "f"(f)); return r;
}
__device__ __forceinline__ void mma_tf32(float* d, const uint32_t* a, const uint32_t* bb){
    asm volatile(
      "mma.sync.aligned.m16n8k8.row.col.f32.tf32.tf32.f32 "
      "{%0,%1,%2,%3}, {%4,%5,%6,%7}, {%8,%9}, {%0,%1,%2,%3};"
      : "+f"(d[0]),"+f"(d[1]),"+f"(d[2]),"+f"(d[3])
      : "r"(a[0]),"r"(a[1]),"r"(a[2]),"r"(a[3]),"r"(bb[0]),"r"(bb[1]));
}

// ---------------------------------------------------------------------------
// Prep kernels
// ---------------------------------------------------------------------------
__global__ void prep_w_kernel(const float* __restrict__ w_out)
{
    int idx = blockIdx.x * 256 + threadIdx.x;
    if (idx < 576*128) g_wT[idx] = __uint_as_float(f2tf32(w_out[idx]));
}
__global__ void prep_woff_kernel(const float* __restrict__ w_off)
{
    int idx = blockIdx.x * 256 + threadIdx.x;
    if (idx >= 576*SBW) return;
    int k = idx / SBW, n = idx % SBW;
    float v = (n < 18) ? __uint_as_float(f2tf32(w_off[k*18 + n])) : 0.f;
    g_wOffP[idx] = v;
}
// x [b][y][x][c] -> g_xT [b][cb][y][x] (float4 of 4 channels)
__global__ __launch_bounds__(256) void transpose_x(const float4* __restrict__ x4)
{
    const int blk  = blockIdx.x;          // b*128 + y
    const int px   = threadIdx.x & 127;
    const int half = threadIdx.x >> 7;
    const int b = blk >> 7, y = blk & 127;
    const int pix16 = (blk * 128 + px) * 16;
    #pragma unroll
    for (int q = 0; q < 8; q++) {
        int cb = half * 8 + q;
        g_xT[((b*16 + cb) << 14) + y*128 + px] = x4[pix16 + cb];
    }
}

// ---------------------------------------------------------------------------
// Kernel 1: offset predictor as tensor-core im2col GEMM
// M=128 pixels/block (one row), N=32 (18 real), K=576 in 18x32 chunks.
// 256 threads = 8 warps (4m x 2n), warp tile 32x16.
// ---------------------------------------------------------------------------
__global__ __launch_bounds__(256) void offset_conv_tc(const float* __restrict__ b_off)
{
    __shared__ float A_sh[2][32*SA];
    __shared__ float Bw_sh[2][32*SBW];

    const int tid  = threadIdx.x;
    const int wid  = tid >> 5;
    const int lane = tid & 31;
    const int g  = lane >> 2;
    const int tc = lane & 3;

    const int p0 = blockIdx.x * 128;
    const int b  = p0 >> 14;
    const int y  = (p0 >> 7) & 127;
    const int pm = tid & 127;
    const int h  = tid >> 7;                  // 0/1: 16 channels each

    const int m_base = (wid >> 1) * 32;
    const int n_base = (wid & 1) * 16;

    float acc[2][2][4];
    #pragma unroll
    for (int nf = 0; nf < 2; nf++) {
        const int c0 = n_base + nf*8 + 2*tc;
        const float bz0 = (c0     < 18) ? b_off[c0]   : 0.f;
        const float bz1 = (c0 + 1 < 18) ? b_off[c0+1] : 0.f;
        #pragma unroll
        for (int mf = 0; mf < 2; mf++) {
            acc[mf][nf][0] = bz0; acc[mf][nf][1] = bz1;
            acc[mf][nf][2] = bz0; acc[mf][nf][3] = bz1;
        }
    }

    #pragma unroll 2
    for (int ch = 0; ch < 18; ch++) {
        const int p     = ch & 1;
        const int tap   = ch >> 1;
        const int chalf = ch & 1;
        const int dy = tap / 3, dx = tap - dy * 3;
        const int yy = y + dy - 1;
        const int xx = pm + dx - 1;
        const bool ok = ((unsigned)yy < 128u) && ((unsigned)xx < 128u);

        // stage B chunk
        for (int i = tid; i < 32*SBW; i += 256)
            Bw_sh[p][i] = g_wOffP[ch * 32 * SBW + i];

        // build A chunk: thread loads 4 float4 (16 channels) of pixel pm
        {
            const int ibase = (b*16 + chalf*8 + h*4) << 14;
            const int off   = yy * 128 + xx;
            #pragma unroll
            for (int q = 0; q < 4; q++) {
                float4 v = ok ? g_xT[ibase + (q << 14) + off]
                              : make_float4(0.f,0.f,0.f,0.f);
                const int k = h*16 + q*4;
                A_sh[p][(k+0)*SA + pm] = __uint_as_float(f2tf32(v.x));
                A_sh[p][(k+1)*SA + pm] = __uint_as_float(f2tf32(v.y));
                A_sh[p][(k+2)*SA + pm] = __uint_as_float(f2tf32(v.z));
                A_sh[p][(k+3)*SA + pm] = __uint_as_float(f2tf32(v.w));
            }
        }
        __syncthreads();

        #pragma unroll
        for (int s = 0; s < 4; s++) {
            const int k0 = s * 8;
            const uint32_t* Ar0 = (const uint32_t*)&A_sh[p][(k0 + tc)     * SA];
            const uint32_t* Ar1 = (const uint32_t*)&A_sh[p][(k0 + tc + 4) * SA];
            const uint32_t* Br0 = (const uint32_t*)&Bw_sh[p][(k0 + tc)     * SBW];
            const uint32_t* Br1 = (const uint32_t*)&Bw_sh[p][(k0 + tc + 4) * SBW];

            uint32_t afr[2][4];
            #pragma unroll
            for (int mf = 0; mf < 2; mf++) {
                const int m = m_base + mf*16 + g;
                afr[mf][0] = Ar0[m];  afr[mf][1] = Ar0[m+8];
                afr[mf][2] = Ar1[m];  afr[mf][3] = Ar1[m+8];
            }
            uint32_t bfr[2][2];
            #pragma unroll
            for (int nf = 0; nf < 2; nf++) {
                const int n = n_base + nf*8 + g;
                bfr[nf][0] = Br0[n];  bfr[nf][1] = Br1[n];
            }
            #pragma unroll
            for (int mf = 0; mf < 2; mf++)
                #pragma unroll
                for (int nf = 0; nf < 2; nf++)
                    mma_tf32(acc[mf][nf], afr[mf], bfr[nf]);
        }
    }

    #pragma unroll
    for (int mf = 0; mf < 2; mf++) {
        const int row = p0 + m_base + mf*16 + g;
        #pragma unroll
        for (int nf = 0; nf < 2; nf++) {
            const int c0 = n_base + nf*8 + 2*tc;
            if (c0 < 18) {
                *(float2*)&g_offsets[row*18 + c0] =
                    make_float2(acc[mf][nf][0], acc[mf][nf][1]);
                *(float2*)&g_offsets[(row+8)*18 + c0] =
                    make_float2(acc[mf][nf][2], acc[mf][nf][3]);
            }
        }
    }
}

// ---------------------------------------------------------------------------
// Kernel 2: fused bilinear sampling (coalesced via g_xT) + tf32 mma GEMM
// Block = 128 pixels x N=128. 512 threads = 16 warps (4m x 4n), tile 32x32.
// Double-buffered A/B, single __syncthreads per K=32 chunk.
// ---------------------------------------------------------------------------
#define SM2_TOTAL (4 * 32 * SA * 4)    // 4 buffers of 32*SA floats = 69632 B

__global__ __launch_bounds__(512) void dconv_gemm_mma(
    const float* __restrict__ b_out, float* __restrict__ out)
{
    extern __shared__ float sm[];
    float* Ab[2] = { sm,            sm + 32*SA   };
    float* Bb[2] = { sm + 2*32*SA,  sm + 3*32*SA };

    const int tid  = threadIdx.x;
    const int wid  = tid >> 5;
    const int lane = tid & 31;
    const int g  = lane >> 2;
    const int tc = lane & 3;

    const int p0 = blockIdx.x * 128;
    const int b  = p0 >> 14;
    const int y  = (p0 >> 7) & 127;
    const int pm = tid & 127;
    const int h  = tid >> 7;                 // 0..3: 8 channels each

    const int m_base = (wid >> 2) * 32;
    const int n_base = (wid & 3) * 32;
    const int gpix = p0 + pm;

    float acc[2][4][4];
    #pragma unroll
    for (int nf = 0; nf < 4; nf++) {
        const int c0 = n_base + nf*8 + 2*tc;
        const float bz0 = b_out[c0], bz1 = b_out[c0+1];
        #pragma unroll
        for (int mf = 0; mf < 2; mf++) {
            acc[mf][nf][0] = bz0; acc[mf][nf][1] = bz1;
            acc[mf][nf][2] = bz0; acc[mf][nf][3] = bz1;
        }
    }

    float wa = 0.f, wbv = 0.f, wcv = 0.f, wdv = 0.f;
    int i00 = 0, i10 = 0, i01 = 0, i11 = 0;   // float4-unit offsets in a plane

    #pragma unroll 2
    for (int ch = 0; ch < 18; ch++) {
        const int p     = ch & 1;
        const int tap   = ch >> 1;
        const int chalf = ch & 1;

        if (chalf == 0) {
            float2 off = *(const float2*)&g_offsets[gpix*18 + tap*2];
            float nx = fminf(fmaxf((float)pm + off.x, 0.f), 127.f);
            float ny = fminf(fmaxf((float)y  + off.y, 0.f), 127.f);
            float x0f = floorf(nx), y0f = floorf(ny);
            float x1f = fminf(x0f + 1.f, 127.f), y1f = fminf(y0f + 1.f, 127.f);
            float lx = nx - x0f, hx = x1f - nx;
            float ly = ny - y0f, hy = y1f - ny;
            wa  = hx*hy; wbv = hx*ly; wcv = lx*hy; wdv = lx*ly;
            int ix0 = (int)x0f, ix1 = (int)x1f, iy0 = (int)y0f, iy1 = (int)y1f;
            i00 = iy0*128 + ix0;  i10 = iy1*128 + ix0;
            i01 = iy0*128 + ix1;  i11 = iy1*128 + ix1;
        }

        // gather 8 channels (2 cb planes) of pixel pm — coalesced across lanes
        uint32_t ov[8];
        {
            const int cb0 = (b*16 + chalf*8 + h*2) << 14;
            #pragma unroll
            for (int j = 0; j < 2; j++) {
                const int base = cb0 + (j << 14);
                float4 a  = g_xT[base + i00];
                float4 bb = g_xT[base + i10];
                float4 cc = g_xT[base + i01];
                float4 dd = g_xT[base + i11];
                ov[j*4+0] = f2tf32(wa*a.x + wbv*bb.x + wcv*cc.x + wdv*dd.x);
                ov[j*4+1] = f2tf32(wa*a.y + wbv*bb.y + wcv*cc.y + wdv*dd.y);
                ov[j*4+2] = f2tf32(wa*a.z + wbv*bb.z + wcv*cc.z + wdv*dd.z);
                ov[j*4+3] = f2tf32(wa*a.w + wbv*bb.w + wcv*cc.w + wdv*dd.w);
            }
        }
        // load B chunk into regs
        float4 bst[2];
        {
            const float4* src = (const float4*)&g_wT[ch * 4096];
            bst[0] = src[tid];  bst[1] = src[tid + 512];
        }

        // store A + B into buffer p (safe: all warps passed previous sync)
        #pragma unroll
        for (int j = 0; j < 2; j++) {
            const int k = h*8 + j*4;
            Ab[p][(k+0)*SA + pm] = __uint_as_float(ov[j*4+0]);
            Ab[p][(k+1)*SA + pm] = __uint_as_float(ov[j*4+1]);
            Ab[p][(k+2)*SA + pm] = __uint_as_float(ov[j*4+2]);
            Ab[p][(k+3)*SA + pm] = __uint_as_float(ov[j*4+3]);
        }
        #pragma unroll
        for (int i = 0; i < 2; i++) {
            const int idx = tid + i*512;
            *(float4*)&Bb[p][(idx >> 5)*SA + (idx & 31)*4] = bst[i];
        }
        __syncthreads();

        #pragma unroll
        for (int s = 0; s < 4; s++) {
            const int k0 = s * 8;
            const uint32_t* Ar0 = (const uint32_t*)&Ab[p][(k0 + tc)     * SA];
            const uint32_t* Ar1 = (const uint32_t*)&Ab[p][(k0 + tc + 4) * SA];
            const uint32_t* Br0 = (const uint32_t*)&Bb[p][(k0 + tc)     * SA];
            const uint32_t* Br1 = (const uint32_t*)&Bb[p][(k0 + tc + 4) * SA];

            uint32_t afr[2][4];
            #pragma unroll
            for (int mf = 0; mf < 2; mf++) {
                const int m = m_base + mf*16 + g;
                afr[mf][0] = Ar0[m];  afr[mf][1] = Ar0[m+8];
                afr[mf][2] = Ar1[m];  afr[mf][3] = Ar1[m+8];
            }
            uint32_t bfr[4][2];
            #pragma unroll
            for (int nf = 0; nf < 4; nf++) {
                const int n = n_base + nf*8 + g;
                bfr[nf][0] = Br0[n];  bfr[nf][1] = Br1[n];
            }
            #pragma unroll
            for (int mf = 0; mf < 2; mf++)
                #pragma unroll
                for (int nf = 0; nf < 4; nf++)
                    mma_tf32(acc[mf][nf], afr[mf], bfr[nf]);
        }
    }

    // epilogue
    #pragma unroll
    for (int mf = 0; mf < 2; mf++) {
        const int row = p0 + m_base + mf*16 + g;
        #pragma unroll
        for (int nf = 0; nf < 4; nf++) {
            const int col = n_base + nf*8 + 2*tc;
            *(float2*)&out[(size_t)row * F_ + col] =
                make_float2(acc[mf][nf][0], acc[mf][nf][1]);
            *(float2*)&out[(size_t)(row + 8) * F_ + col] =
                make_float2(acc[mf][nf][2], acc[mf][nf][3]);
        }
    }
}

// ---------------------------------------------------------------------------
extern "C" void kernel_launch(void* const* d_in, const int* in_sizes, int n_in,
                              void* d_out, int out_size)
{
    const float* x     = (const float*)d_in[0];
    const float* w_off = (const float*)d_in[1];
    const float* b_off = (const float*)d_in[2];
    const float* w_out = (const float*)d_in[3];
    const float* b_out = (const float*)d_in[4];
    float* out = (float*)d_out;

    cudaFuncSetAttribute(dconv_gemm_mma,
                         cudaFuncAttributeMaxDynamicSharedMemorySize, SM2_TOTAL);

    prep_w_kernel   <<<(576*128 + 255)/256, 256>>>(w_out);
    prep_woff_kernel<<<(576*SBW + 255)/256, 256>>>(w_off);
    transpose_x     <<<B_ * H_, 256>>>((const float4*)x);
    offset_conv_tc  <<<B_ * H_, 256>>>(b_off);
    dconv_gemm_mma  <<<(B_*H_*W_)/128, 512, SM2_TOTAL>>>(b_out, out);
}

// round 7
// speedup vs baseline: 2.0533x; 1.1950x over previous
#include <cuda_runtime.h>
#include <cstdint>

#define B_  8
#define H_  128
#define W_  128
#define C_  64
#define F_  128
#define SA  136   // smem row stride (floats); 136%32==8 -> conflict-free frags

// scratch
__device__ float  g_offsets[B_*H_*W_*18];   // predicted offsets [B,H,W,18]
__device__ float  g_wT[576*128];            // w_out, tf32-rounded [k][n]
__device__ float4 g_xT[B_*16*H_*W_];        // x channel-blocked [b][c/4][y][x]

__device__ __forceinline__ uint32_t f2tf32(float f){
    uint32_t r; asm("cvt.rna.tf32.f32 %0, %1;" : "=r"(r) : "f"(f)); return r;
}
__device__ __forceinline__ void mma_tf32(float* d, const uint32_t* a, const uint32_t* bb){
    asm volatile(
      "mma.sync.aligned.m16n8k8.row.col.f32.tf32.tf32.f32 "
      "{%0,%1,%2,%3}, {%4,%5,%6,%7}, {%8,%9}, {%0,%1,%2,%3};"
      : "+f"(d[0]),"+f"(d[1]),"+f"(d[2]),"+f"(d[3])
      : "r"(a[0]),"r"(a[1]),"r"(a[2]),"r"(a[3]),"r"(bb[0]),"r"(bb[1]));
}

// ---------------------------------------------------------------------------
// Prep kernels
// ---------------------------------------------------------------------------
__global__ void prep_w_kernel(const float* __restrict__ w_out)
{
    int idx = blockIdx.x * 256 + threadIdx.x;
    if (idx < 576*128) g_wT[idx] = __uint_as_float(f2tf32(w_out[idx]));
}
// x [b][y][x][c] -> g_xT [b][cb][y][x] (float4 of 4 channels)
__global__ __launch_bounds__(256) void transpose_x(const float4* __restrict__ x4)
{
    const int blk  = blockIdx.x;          // b*128 + y
    const int px   = threadIdx.x & 127;
    const int half = threadIdx.x >> 7;
    const int b = blk >> 7, y = blk & 127;
    const int pix16 = (blk * 128 + px) * 16;
    #pragma unroll
    for (int q = 0; q < 8; q++) {
        int cb = half * 8 + q;
        g_xT[((b*16 + cb) << 14) + y*128 + px] = x4[pix16 + cb];
    }
}

// ---------------------------------------------------------------------------
// Kernel 1: 3x3 SAME conv, 64 -> 18 channels, fp32 (accuracy-critical)
// ---------------------------------------------------------------------------
__global__ __launch_bounds__(128) void offset_conv_kernel(
    const float* __restrict__ x, const float* __restrict__ w_off,
    const float* __restrict__ b_off)
{
    __shared__ float row_sh[130 * 68];
    __shared__ float w_sh[3 * 64 * 18];

    const int t  = threadIdx.x;
    const int by = blockIdx.x;
    const int b  = by / H_;
    const int y  = by % H_;

    float acc[18];
    #pragma unroll
    for (int oc = 0; oc < 18; oc++) acc[oc] = b_off[oc];

    for (int dy = 0; dy < 3; dy++) {
        __syncthreads();
        const int yy = y + dy - 1;
        for (int i = t; i < 3 * 64 * 18; i += 128)
            w_sh[i] = w_off[dy * 3 * 64 * 18 + i];
        if (t < 2) {
            const int e = (t == 0) ? 0 : 129;
            float4 z = make_float4(0.f, 0.f, 0.f, 0.f);
            #pragma unroll
            for (int c = 0; c < 64; c += 4)
                *(float4*)&row_sh[e * 68 + c] = z;
        }
        {
            float4* dst = (float4*)&row_sh[(t + 1) * 68];
            if (yy >= 0 && yy < H_) {
                const float4* src = (const float4*)&x[((b * H_ + yy) * W_ + t) * C_];
                #pragma unroll
                for (int c = 0; c < 16; c++) dst[c] = src[c];
            } else {
                float4 z = make_float4(0.f, 0.f, 0.f, 0.f);
                #pragma unroll
                for (int c = 0; c < 16; c++) dst[c] = z;
            }
        }
        __syncthreads();

        for (int dx = 0; dx < 3; dx++) {
            const float* wp = &w_sh[dx * 64 * 18];
            const float* rp = &row_sh[(t + dx) * 68];
            for (int c = 0; c < 64; c++) {
                const float xv = rp[c];
                #pragma unroll
                for (int oc = 0; oc < 18; oc++)
                    acc[oc] += xv * wp[c * 18 + oc];
            }
        }
    }
    float* op = &g_offsets[((b * H_ + y) * W_ + t) * 18];
    #pragma unroll
    for (int oc = 0; oc < 18; oc++) op[oc] = acc[oc];
}

// ---------------------------------------------------------------------------
// Kernel 2: fused bilinear sampling + tf32 mma GEMM, register-pipelined.
// Block = 128 pixels x N=128. 512 threads = 16 warps (4m x 4n), tile 32x32.
// Schedule per chunk ch:
//   [STS A(ch)+B(ch) from regs] [sync] [LDG gathers+B(ch+1)] [MMA(ch)]
//   [weight ch+1 -> regs]
// Gather/B-load latency for ch+1 is hidden behind MMA(ch) + frag LDS.
// ---------------------------------------------------------------------------
#define SM2_TOTAL (4 * 32 * SA * 4)    // 69632 B (proven config)

__global__ __launch_bounds__(512) void dconv_gemm_mma(
    const float* __restrict__ b_out, float* __restrict__ out)
{
    extern __shared__ float sm[];
    float* Abuf[2] = { sm,            sm + 32*SA   };
    float* Bbuf[2] = { sm + 2*32*SA,  sm + 3*32*SA };

    const int tid  = threadIdx.x;
    const int wid  = tid >> 5;
    const int lane = tid & 31;
    const int g  = lane >> 2;
    const int tc = lane & 3;

    const int p0 = blockIdx.x * 128;
    const int b  = p0 >> 14;
    const int y  = (p0 >> 7) & 127;
    const int pm = tid & 127;             // pixel in tile
    const int h  = tid >> 7;              // 0..3 -> 8 channels each

    const int m_base = (wid >> 2) * 32;
    const int n_base = (wid & 3) * 32;
    const float* offp = &g_offsets[(p0 + pm) * 18];

    float acc[2][4][4];
    #pragma unroll
    for (int nf = 0; nf < 4; nf++) {
        const int c0 = n_base + nf*8 + 2*tc;
        const float bz0 = __ldg(&b_out[c0]), bz1 = __ldg(&b_out[c0+1]);
        #pragma unroll
        for (int mf = 0; mf < 2; mf++) {
            acc[mf][nf][0] = bz0; acc[mf][nf][1] = bz1;
            acc[mf][nf][2] = bz0; acc[mf][nf][3] = bz1;
        }
    }

    // per-tap coordinate state
    float wa=0.f, wbv=0.f, wcv=0.f, wdv=0.f;
    int i00=0, i10=0, i01=0, i11=0;

    #define COORDS(off) { \
        float nx = fminf(fmaxf((float)pm + (off).x, 0.f), 127.f); \
        float ny = fminf(fmaxf((float)y  + (off).y, 0.f), 127.f); \
        float x0f = floorf(nx), y0f = floorf(ny); \
        float x1f = fminf(x0f + 1.f, 127.f), y1f = fminf(y0f + 1.f, 127.f); \
        float lx = nx - x0f, hx = x1f - nx; \
        float ly = ny - y0f, hy = y1f - ny; \
        wa = hx*hy; wbv = hx*ly; wcv = lx*hy; wdv = lx*ly; \
        int ix0 = (int)x0f, ix1 = (int)x1f, iy0 = (int)y0f, iy1 = (int)y1f; \
        i00 = iy0*128 + ix0;  i10 = iy1*128 + ix0; \
        i01 = iy0*128 + ix1;  i11 = iy1*128 + ix1; }

    // in-flight raw data registers
    float4 ra0, rb0, rc0, rd0, ra1, rb1, rc1, rd1;   // corners, 2 planes
    float4 bst0, bst1;                               // B chunk stage
    uint32_t vv[8];

    #define GATHER(chv) { \
        const int cb0 = (b*16 + ((chv)&1)*8 + h*2) << 14; \
        ra0 = g_xT[cb0 + i00]; rb0 = g_xT[cb0 + i10]; \
        rc0 = g_xT[cb0 + i01]; rd0 = g_xT[cb0 + i11]; \
        const int cb1 = cb0 + (1 << 14); \
        ra1 = g_xT[cb1 + i00]; rb1 = g_xT[cb1 + i10]; \
        rc1 = g_xT[cb1 + i01]; rd1 = g_xT[cb1 + i11]; }

    #define BLOAD(chv) { \
        const float4* src = (const float4*)&g_wT[(chv) * 4096]; \
        bst0 = src[tid];  bst1 = src[tid + 512]; }

    #define WEIGHT() { \
        vv[0]=f2tf32(wa*ra0.x + wbv*rb0.x + wcv*rc0.x + wdv*rd0.x); \
        vv[1]=f2tf32(wa*ra0.y + wbv*rb0.y + wcv*rc0.y + wdv*rd0.y); \
        vv[2]=f2tf32(wa*ra0.z + wbv*rb0.z + wcv*rc0.z + wdv*rd0.z); \
        vv[3]=f2tf32(wa*ra0.w + wbv*rb0.w + wcv*rc0.w + wdv*rd0.w); \
        vv[4]=f2tf32(wa*ra1.x + wbv*rb1.x + wcv*rc1.x + wdv*rd1.x); \
        vv[5]=f2tf32(wa*ra1.y + wbv*rb1.y + wcv*rc1.y + wdv*rd1.y); \
        vv[6]=f2tf32(wa*ra1.z + wbv*rb1.z + wcv*rc1.z + wdv*rd1.z); \
        vv[7]=f2tf32(wa*ra1.w + wbv*rb1.w + wcv*rc1.w + wdv*rd1.w); }

    // ---- prologue: fill pipeline for ch=0 ----
    float2 curoff  = *(const float2*)(offp + 0);
    float2 nextoff = *(const float2*)(offp + 2);    // tap 1
    COORDS(curoff);
    GATHER(0);
    BLOAD(0);
    WEIGHT();                        // stalls on first gathers only

    for (int ch = 0; ch < 18; ch++) {
        const int p = ch & 1;
        float* Ab = Abuf[p];
        float* Bb = Bbuf[p];

        // 1. store staged A(ch) and B(ch) into buffer p
        #pragma unroll
        for (int j = 0; j < 2; j++) {
            const int k = h*8 + j*4;
            Ab[(k+0)*SA + pm] = __uint_as_float(vv[j*4+0]);
            Ab[(k+1)*SA + pm] = __uint_as_float(vv[j*4+1]);
            Ab[(k+2)*SA + pm] = __uint_as_float(vv[j*4+2]);
            Ab[(k+3)*SA + pm] = __uint_as_float(vv[j*4+3]);
        }
        *(float4*)&Bb[(tid >> 5)*SA + (tid & 31)*4] = bst0;
        {
            const int idx = tid + 512;
            *(float4*)&Bb[(idx >> 5)*SA + (idx & 31)*4] = bst1;
        }
        __syncthreads();

        // 2. issue loads for ch+1 (latency hidden behind MMA below)
        if (ch + 1 < 18) {
            if (((ch + 1) & 1) == 0) {          // new tap starts at even chunk
                COORDS(nextoff);
                if (ch + 1 <= 14)               // prefetch tap after that
                    nextoff = *(const float2*)(offp + ((ch+3) >> 1) * 2);
            }
            GATHER(ch + 1);
            BLOAD(ch + 1);
        }

        // 3. MMA(ch)
        #pragma unroll
        for (int s = 0; s < 4; s++) {
            const int k0 = s * 8;
            const uint32_t* Ar0 = (const uint32_t*)&Ab[(k0 + tc)     * SA];
            const uint32_t* Ar1 = (const uint32_t*)&Ab[(k0 + tc + 4) * SA];
            const uint32_t* Br0 = (const uint32_t*)&Bb[(k0 + tc)     * SA];
            const uint32_t* Br1 = (const uint32_t*)&Bb[(k0 + tc + 4) * SA];

            uint32_t afr[2][4];
            #pragma unroll
            for (int mf = 0; mf < 2; mf++) {
                const int m = m_base + mf*16 + g;
                afr[mf][0] = Ar0[m];  afr[mf][1] = Ar0[m+8];
                afr[mf][2] = Ar1[m];  afr[mf][3] = Ar1[m+8];
            }
            uint32_t bfr[4][2];
            #pragma unroll
            for (int nf = 0; nf < 4; nf++) {
                const int n = n_base + nf*8 + g;
                bfr[nf][0] = Br0[n];  bfr[nf][1] = Br1[n];
            }
            #pragma unroll
            for (int mf = 0; mf < 2; mf++)
                #pragma unroll
                for (int nf = 0; nf < 4; nf++)
                    mma_tf32(acc[mf][nf], afr[mf], bfr[nf]);
        }

        // 4. weight+convert ch+1 samples into vv regs
        if (ch + 1 < 18) { WEIGHT(); }
    }

    // ---- epilogue ----
    #pragma unroll
    for (int mf = 0; mf < 2; mf++) {
        const int row = p0 + m_base + mf*16 + g;
        #pragma unroll
        for (int nf = 0; nf < 4; nf++) {
            const int col = n_base + nf*8 + 2*tc;
            *(float2*)&out[(size_t)row * F_ + col] =
                make_float2(acc[mf][nf][0], acc[mf][nf][1]);
            *(float2*)&out[(size_t)(row + 8) * F_ + col] =
                make_float2(acc[mf][nf][2], acc[mf][nf][3]);
        }
    }
}

// ---------------------------------------------------------------------------
extern "C" void kernel_launch(void* const* d_in, const int* in_sizes, int n_in,
                              void* d_out, int out_size)
{
    const float* x     = (const float*)d_in[0];
    const float* w_off = (const float*)d_in[1];
    const float* b_off = (const float*)d_in[2];
    const float* w_out = (const float*)d_in[3];
    const float* b_out = (const float*)d_in[4];
    float* out = (float*)d_out;

    cudaFuncSetAttribute(dconv_gemm_mma,
                         cudaFuncAttributeMaxDynamicSharedMemorySize, SM2_TOTAL);

    prep_w_kernel     <<<(576*128 + 255)/256, 256>>>(w_out);
    transpose_x       <<<B_ * H_, 256>>>((const float4*)x);
    offset_conv_kernel<<<B_ * H_, 128>>>(x, w_off, b_off);
    dconv_gemm_mma    <<<(B_*H_*W_)/128, 512, SM2_TOTAL>>>(b_out, out);
}